// round 2
// baseline (speedup 1.0000x reference)
#include <cuda_runtime.h>
#include <cstdint>

#define NN      100000
#define NE      600000
#define HID     128

// Scratch (device globals only — no allocation allowed)
__device__ float g_uv[(size_t)NN * 256];   // per-node u (cols 0..127) and v (cols 128..255)
__device__ float g_exp[NE];                // per-edge exp(score)
__device__ float g_sum[NN];                // per-node sum of exp

// ---------------------------------------------------------------------------
// K0: out = x ; g_sum = 0
// ---------------------------------------------------------------------------
__global__ void k_init(const float* __restrict__ x, float* __restrict__ out) {
    long i = (long)blockIdx.x * blockDim.x + threadIdx.x;
    long stride = (long)gridDim.x * blockDim.x;
    const long n4 = (long)NN * HID / 4;
    const float4* x4 = (const float4*)x;
    float4* o4 = (float4*)out;
    for (long j = i; j < n4; j += stride) o4[j] = x4[j];
    for (long j = i; j < NN; j += stride) g_sum[j] = 0.0f;
}

// ---------------------------------------------------------------------------
// K1: SGEMM  g_uv[i][q*128 + j] = sum_k x[i][k] * W1[q*128 + k][j]
//   q=0 -> u (src weights, W1 rows 0..127), q=1 -> v (tgt weights, rows 128..255)
//   Block tile: 128(M) x 128(N), K=128, BK=16, 256 threads, 8x8 microtile.
// ---------------------------------------------------------------------------
__global__ __launch_bounds__(256, 2) void k_gemm(const float* __restrict__ A,
                                                 const float* __restrict__ W1) {
    __shared__ float As[16][128];   // As[k][m]
    __shared__ float Bs[16][128];   // Bs[k][n]

    const int q  = blockIdx.y;
    const int m0 = blockIdx.x * 128;
    const float* B = W1 + (size_t)q * 128 * 128;   // 128x128 row-major chunk

    const int t  = threadIdx.x;
    const int tx = t & 15;      // 0..15 -> n
    const int ty = t >> 4;      // 0..15 -> m

    float acc[8][8];
    #pragma unroll
    for (int i = 0; i < 8; i++)
        #pragma unroll
        for (int j = 0; j < 8; j++) acc[i][j] = 0.0f;

    for (int k0 = 0; k0 < 128; k0 += 16) {
        // Load A tile 128x16 (transposed into As[k][m]); 512 float4, 2 per thread
        #pragma unroll
        for (int r = 0; r < 2; r++) {
            int idx = t + r * 256;          // 0..511
            int row = idx >> 2;             // 0..127
            int c4  = idx & 3;              // which float4 of the 16-wide k chunk
            float4 val = make_float4(0.f, 0.f, 0.f, 0.f);
            int grow = m0 + row;
            if (grow < NN)
                val = *(const float4*)(A + (size_t)grow * HID + k0 + c4 * 4);
            As[c4 * 4 + 0][row] = val.x;
            As[c4 * 4 + 1][row] = val.y;
            As[c4 * 4 + 2][row] = val.z;
            As[c4 * 4 + 3][row] = val.w;
        }
        // Load B tile 16x128; 512 float4, 2 per thread, coalesced
        #pragma unroll
        for (int r = 0; r < 2; r++) {
            int idx = t + r * 256;          // 0..511
            int k   = idx >> 5;             // 0..15
            int j4  = idx & 31;             // 0..31
            *(float4*)&Bs[k][j4 * 4] =
                *(const float4*)(B + (size_t)(k0 + k) * 128 + j4 * 4);
        }
        __syncthreads();

        #pragma unroll
        for (int kk = 0; kk < 16; kk++) {
            float a[8], b[8];
            *(float4*)&a[0] = *(float4*)&As[kk][ty * 8];
            *(float4*)&a[4] = *(float4*)&As[kk][ty * 8 + 4];
            *(float4*)&b[0] = *(float4*)&Bs[kk][tx * 8];
            *(float4*)&b[4] = *(float4*)&Bs[kk][tx * 8 + 4];
            #pragma unroll
            for (int i = 0; i < 8; i++)
                #pragma unroll
                for (int j = 0; j < 8; j++)
                    acc[i][j] = fmaf(a[i], b[j], acc[i][j]);
        }
        __syncthreads();
    }

    // Store
    #pragma unroll
    for (int i = 0; i < 8; i++) {
        int grow = m0 + ty * 8 + i;
        if (grow < NN) {
            float* dst = g_uv + (size_t)grow * 256 + q * 128 + tx * 8;
            *(float4*)dst       = *(float4*)&acc[i][0];
            *(float4*)(dst + 4) = *(float4*)&acc[i][4];
        }
    }
}

// ---------------------------------------------------------------------------
// K2: per-edge score. One warp per edge.
//   hidden = relu(u[src] + v[tgt] + w*W1c + b1); score = hidden.W2 + b2
//   g_exp[e] = exp(score); atomicAdd(g_sum[tgt], g_exp[e])
//   edge_index is INT32 on the wire (JAX x64 disabled downcasts int64).
// ---------------------------------------------------------------------------
__global__ __launch_bounds__(256) void k_edge_score(
    const int* __restrict__ ei, const float* __restrict__ ew,
    const float* __restrict__ W1, const float* __restrict__ b1,
    const float* __restrict__ W2, const float* __restrict__ b2)
{
    __shared__ float sW1c[HID], sb1[HID], sW2[HID];
    const int t = threadIdx.x;
    if (t < HID) {
        sW1c[t] = W1[256 * HID + t];   // last row of W1 (edge-weight row)
        sb1[t]  = b1[t];
        sW2[t]  = W2[t];
    }
    __syncthreads();

    const int warp = t >> 5, lane = t & 31;
    const long e = (long)blockIdx.x * 8 + warp;
    if (e >= NE) return;

    const int src = ei[e];
    const int tgt = ei[NE + e];
    const float w = ew[e];

    float4 u = ((const float4*)(g_uv + (size_t)src * 256))[lane];
    float4 v = ((const float4*)(g_uv + (size_t)tgt * 256 + 128))[lane];
    float4 wc = *(const float4*)&sW1c[lane * 4];
    float4 bb = *(const float4*)&sb1[lane * 4];
    float4 w2 = *(const float4*)&sW2[lane * 4];

    float h0 = fmaxf(u.x + v.x + w * wc.x + bb.x, 0.0f);
    float h1 = fmaxf(u.y + v.y + w * wc.y + bb.y, 0.0f);
    float h2 = fmaxf(u.z + v.z + w * wc.z + bb.z, 0.0f);
    float h3 = fmaxf(u.w + v.w + w * wc.w + bb.w, 0.0f);

    float p = h0 * w2.x + h1 * w2.y + h2 * w2.z + h3 * w2.w;
    #pragma unroll
    for (int o = 16; o; o >>= 1) p += __shfl_xor_sync(0xffffffffu, p, o);

    if (lane == 0) {
        float es = expf(p + b2[0]);
        g_exp[e] = es;
        atomicAdd(&g_sum[tgt], es);
    }
}

// ---------------------------------------------------------------------------
// K3: per-edge aggregate. One warp per edge.
//   alpha = g_exp[e] / max(g_sum[tgt], 1e-12); out[tgt] += alpha * x[src]
//   Vector reduction (red.global.add.v4.f32, sm_90+) -> 4x fewer REDG ops.
// ---------------------------------------------------------------------------
__global__ __launch_bounds__(256) void k_edge_agg(
    const int* __restrict__ ei, const float* __restrict__ x,
    float* __restrict__ out)
{
    const int t = threadIdx.x;
    const int warp = t >> 5, lane = t & 31;
    const long e = (long)blockIdx.x * 8 + warp;
    if (e >= NE) return;

    const int src = ei[e];
    const int tgt = ei[NE + e];
    const float alpha = g_exp[e] / fmaxf(g_sum[tgt], 1e-12f);

    float4 hx = ((const float4*)(x + (size_t)src * HID))[lane];
    float* dst = out + (size_t)tgt * HID + lane * 4;
    asm volatile("red.global.add.v4.f32 [%0], {%1, %2, %3, %4};"
                 :: "l"(dst), "f"(alpha * hx.x), "f"(alpha * hx.y),
                    "f"(alpha * hx.z), "f"(alpha * hx.w)
                 : "memory");
}

// ---------------------------------------------------------------------------
extern "C" void kernel_launch(void* const* d_in, const int* in_sizes, int n_in,
                              void* d_out, int out_size)
{
    const float* x  = (const float*)d_in[0];
    const int*   ei = (const int*)d_in[1];
    const float* ew = (const float*)d_in[2];
    const float* W1 = (const float*)d_in[3];
    const float* b1 = (const float*)d_in[4];
    const float* W2 = (const float*)d_in[5];
    const float* b2 = (const float*)d_in[6];
    float* out = (float*)d_out;

    k_init<<<2048, 256>>>(x, out);

    dim3 gg((NN + 127) / 128, 2);
    k_gemm<<<gg, 256>>>(x, W1);

    k_edge_score<<<(NE + 7) / 8, 256>>>(ei, ew, W1, b1, W2, b2);
    k_edge_agg<<<(NE + 7) / 8, 256>>>(ei, x, out);
}

// round 3
// speedup vs baseline: 1.1406x; 1.1406x over previous
#include <cuda_runtime.h>
#include <cstdint>

#define NN      100000
#define NE      600000
#define HID     128

// Scratch (device globals only — no allocation allowed)
__device__ float g_uv[(size_t)NN * 256];    // per-node u (cols 0..127) and v (cols 128..255)
__device__ float g_num[(size_t)NN * HID];   // numerator: sum_e exp_e * x[src]
__device__ float g_sum[NN];                 // denominator: sum_e exp_e

// ---------------------------------------------------------------------------
// K0: zero g_num, g_sum
// ---------------------------------------------------------------------------
__global__ void k_zero() {
    long i = (long)blockIdx.x * blockDim.x + threadIdx.x;
    long stride = (long)gridDim.x * blockDim.x;
    const long n4 = (long)NN * HID / 4;
    float4* n4p = (float4*)g_num;
    const float4 z = make_float4(0.f, 0.f, 0.f, 0.f);
    for (long j = i; j < n4; j += stride) n4p[j] = z;
    for (long j = i; j < NN; j += stride) g_sum[j] = 0.0f;
}

// ---------------------------------------------------------------------------
// K1: SGEMM with packed fma.rn.f32x2 (sm_103a FFMA2: 2 fp32 MACs / instr)
//   g_uv[i][q*128 + j] = sum_k x[i][k] * W1[q*128 + k][j]
//   Block tile 128x128, K-step 16, 256 threads, 8x8 microtile.
// ---------------------------------------------------------------------------
__global__ __launch_bounds__(256, 2) void k_gemm(const float* __restrict__ A,
                                                 const float* __restrict__ W1) {
    __shared__ float As[16][128];   // As[k][m]
    __shared__ float Bs[16][128];   // Bs[k][n]

    const int q  = blockIdx.y;
    const int m0 = blockIdx.x * 128;
    const float* B = W1 + (size_t)q * 128 * 128;

    const int t  = threadIdx.x;
    const int tx = t & 15;      // n / 8
    const int ty = t >> 4;      // m / 8

    // acc2[i][j] holds the packed pair (n = tx*8+2j, tx*8+2j+1) for row m = ty*8+i
    unsigned long long acc2[8][4];
    #pragma unroll
    for (int i = 0; i < 8; i++)
        #pragma unroll
        for (int j = 0; j < 4; j++) acc2[i][j] = 0ULL;

    for (int k0 = 0; k0 < 128; k0 += 16) {
        #pragma unroll
        for (int r = 0; r < 2; r++) {
            int idx = t + r * 256;
            int row = idx >> 2;
            int c4  = idx & 3;
            float4 val = make_float4(0.f, 0.f, 0.f, 0.f);
            int grow = m0 + row;
            if (grow < NN)
                val = *(const float4*)(A + (size_t)grow * HID + k0 + c4 * 4);
            As[c4 * 4 + 0][row] = val.x;
            As[c4 * 4 + 1][row] = val.y;
            As[c4 * 4 + 2][row] = val.z;
            As[c4 * 4 + 3][row] = val.w;
        }
        #pragma unroll
        for (int r = 0; r < 2; r++) {
            int idx = t + r * 256;
            int k   = idx >> 5;
            int j4  = idx & 31;
            *(float4*)&Bs[k][j4 * 4] =
                *(const float4*)(B + (size_t)(k0 + k) * 128 + j4 * 4);
        }
        __syncthreads();

        #pragma unroll
        for (int kk = 0; kk < 16; kk++) {
            float a[8];
            *(float4*)&a[0] = *(float4*)&As[kk][ty * 8];
            *(float4*)&a[4] = *(float4*)&As[kk][ty * 8 + 4];
            // b pairs as 64-bit packed values (Bs row is 16B aligned at tx*8)
            ulonglong2 blo = *(ulonglong2*)&Bs[kk][tx * 8];
            ulonglong2 bhi = *(ulonglong2*)&Bs[kk][tx * 8 + 4];
            unsigned long long b2[4] = {blo.x, blo.y, bhi.x, bhi.y};

            #pragma unroll
            for (int i = 0; i < 8; i++) {
                unsigned long long a2;
                asm("mov.b64 %0, {%1, %1};" : "=l"(a2) : "f"(a[i]));
                #pragma unroll
                for (int j = 0; j < 4; j++)
                    asm("fma.rn.f32x2 %0, %1, %2, %0;"
                        : "+l"(acc2[i][j]) : "l"(a2), "l"(b2[j]));
            }
        }
        __syncthreads();
    }

    #pragma unroll
    for (int i = 0; i < 8; i++) {
        int grow = m0 + ty * 8 + i;
        if (grow < NN) {
            float out[8];
            #pragma unroll
            for (int j = 0; j < 4; j++)
                asm("mov.b64 {%0, %1}, %2;"
                    : "=f"(out[2 * j]), "=f"(out[2 * j + 1]) : "l"(acc2[i][j]));
            float* dst = g_uv + (size_t)grow * 256 + q * 128 + tx * 8;
            *(float4*)dst       = *(float4*)&out[0];
            *(float4*)(dst + 4) = *(float4*)&out[4];
        }
    }
}

// ---------------------------------------------------------------------------
// K2: fused per-edge pass. One warp per edge.
//   hidden = relu(u[src] + v[tgt] + w*W1c + b1); score = hidden.W2 + b2
//   es = exp(score); g_sum[tgt] += es; g_num[tgt] += es * x[src]
// ---------------------------------------------------------------------------
__global__ __launch_bounds__(256) void k_edge(
    const int* __restrict__ ei, const float* __restrict__ ew,
    const float* __restrict__ x,
    const float* __restrict__ W1, const float* __restrict__ b1,
    const float* __restrict__ W2, const float* __restrict__ b2)
{
    __shared__ float sW1c[HID], sb1[HID], sW2[HID];
    __shared__ float sb2;
    const int t = threadIdx.x;
    if (t < HID) {
        sW1c[t] = W1[256 * HID + t];
        sb1[t]  = b1[t];
        sW2[t]  = W2[t];
    }
    if (t == 0) sb2 = b2[0];
    __syncthreads();

    const int warp = t >> 5, lane = t & 31;
    const long e = (long)blockIdx.x * 8 + warp;
    if (e >= NE) return;

    const int src = ei[e];
    const int tgt = ei[NE + e];
    const float w = ew[e];

    float4 u = ((const float4*)(g_uv + (size_t)src * 256))[lane];
    float4 v = ((const float4*)(g_uv + (size_t)tgt * 256 + 128))[lane];
    float4 wc = *(const float4*)&sW1c[lane * 4];
    float4 bb = *(const float4*)&sb1[lane * 4];
    float4 w2 = *(const float4*)&sW2[lane * 4];

    float h0 = fmaxf(fmaf(w, wc.x, u.x + v.x) + bb.x, 0.0f);
    float h1 = fmaxf(fmaf(w, wc.y, u.y + v.y) + bb.y, 0.0f);
    float h2 = fmaxf(fmaf(w, wc.z, u.z + v.z) + bb.z, 0.0f);
    float h3 = fmaxf(fmaf(w, wc.w, u.w + v.w) + bb.w, 0.0f);

    float p = h0 * w2.x + h1 * w2.y + h2 * w2.z + h3 * w2.w;
    #pragma unroll
    for (int o = 16; o; o >>= 1) p += __shfl_xor_sync(0xffffffffu, p, o);

    const float es = expf(p + sb2);
    if (lane == 0) atomicAdd(&g_sum[tgt], es);

    float4 hx = ((const float4*)(x + (size_t)src * HID))[lane];
    float* dst = g_num + (size_t)tgt * HID + lane * 4;
    asm volatile("red.global.add.v4.f32 [%0], {%1, %2, %3, %4};"
                 :: "l"(dst), "f"(es * hx.x), "f"(es * hx.y),
                    "f"(es * hx.z), "f"(es * hx.w)
                 : "memory");
}

// ---------------------------------------------------------------------------
// K3: normalize. out = x + g_num / max(g_sum, 1e-12)
// ---------------------------------------------------------------------------
__global__ void k_norm(const float* __restrict__ x, float* __restrict__ out) {
    long i = (long)blockIdx.x * blockDim.x + threadIdx.x;
    long stride = (long)gridDim.x * blockDim.x;
    const long n4 = (long)NN * HID / 4;
    const float4* x4 = (const float4*)x;
    const float4* num4 = (const float4*)g_num;
    float4* o4 = (float4*)out;
    for (long j = i; j < n4; j += stride) {
        int node = (int)(j >> 5);           // 32 float4 per node row
        float inv = 1.0f / fmaxf(g_sum[node], 1e-12f);
        float4 xv = x4[j];
        float4 nv = num4[j];
        o4[j] = make_float4(fmaf(nv.x, inv, xv.x), fmaf(nv.y, inv, xv.y),
                            fmaf(nv.z, inv, xv.z), fmaf(nv.w, inv, xv.w));
    }
}

// ---------------------------------------------------------------------------
extern "C" void kernel_launch(void* const* d_in, const int* in_sizes, int n_in,
                              void* d_out, int out_size)
{
    const float* x  = (const float*)d_in[0];
    const int*   ei = (const int*)d_in[1];
    const float* ew = (const float*)d_in[2];
    const float* W1 = (const float*)d_in[3];
    const float* b1 = (const float*)d_in[4];
    const float* W2 = (const float*)d_in[5];
    const float* b2 = (const float*)d_in[6];
    float* out = (float*)d_out;

    k_zero<<<2048, 256>>>();

    dim3 gg((NN + 127) / 128, 2);
    k_gemm<<<gg, 256>>>(x, W1);

    k_edge<<<(NE + 7) / 8, 256>>>(ei, ew, x, W1, b1, W2, b2);
    k_norm<<<2048, 256>>>(x, out);
}

// round 4
// speedup vs baseline: 1.1705x; 1.0263x over previous
#include <cuda_runtime.h>
#include <cstdint>

#define NN      100000
#define NE      600000
#define HID     128
#define EPW     4            // edges per warp in k_edge

// Scratch (device globals only — no allocation allowed)
__device__ float g_uv[(size_t)NN * 256];    // per-node u (cols 0..127) and v (cols 128..255)
__device__ float g_num[(size_t)NN * HID];   // numerator: sum_e exp_e * x[src]
__device__ float g_sum[NN];                 // denominator: sum_e exp_e

// ---------------------------------------------------------------------------
// K0: zero g_num, g_sum
// ---------------------------------------------------------------------------
__global__ void k_zero() {
    long i = (long)blockIdx.x * blockDim.x + threadIdx.x;
    long stride = (long)gridDim.x * blockDim.x;
    const long n4 = (long)NN * HID / 4;
    float4* n4p = (float4*)g_num;
    const float4 z = make_float4(0.f, 0.f, 0.f, 0.f);
    for (long j = i; j < n4; j += stride) n4p[j] = z;
    for (long j = i; j < NN; j += stride) g_sum[j] = 0.0f;
}

// ---------------------------------------------------------------------------
// K1: SGEMM with packed fma.rn.f32x2 (sm_103a FFMA2: 2 fp32 MACs / instr)
//   g_uv[i][q*128 + j] = sum_k x[i][k] * W1[q*128 + k][j]
// ---------------------------------------------------------------------------
__global__ __launch_bounds__(256, 2) void k_gemm(const float* __restrict__ A,
                                                 const float* __restrict__ W1) {
    __shared__ float As[16][128];   // As[k][m]
    __shared__ float Bs[16][128];   // Bs[k][n]

    const int q  = blockIdx.y;
    const int m0 = blockIdx.x * 128;
    const float* B = W1 + (size_t)q * 128 * 128;

    const int t  = threadIdx.x;
    const int tx = t & 15;      // n / 8
    const int ty = t >> 4;      // m / 8

    unsigned long long acc2[8][4];
    #pragma unroll
    for (int i = 0; i < 8; i++)
        #pragma unroll
        for (int j = 0; j < 4; j++) acc2[i][j] = 0ULL;

    for (int k0 = 0; k0 < 128; k0 += 16) {
        #pragma unroll
        for (int r = 0; r < 2; r++) {
            int idx = t + r * 256;
            int row = idx >> 2;
            int c4  = idx & 3;
            float4 val = make_float4(0.f, 0.f, 0.f, 0.f);
            int grow = m0 + row;
            if (grow < NN)
                val = *(const float4*)(A + (size_t)grow * HID + k0 + c4 * 4);
            As[c4 * 4 + 0][row] = val.x;
            As[c4 * 4 + 1][row] = val.y;
            As[c4 * 4 + 2][row] = val.z;
            As[c4 * 4 + 3][row] = val.w;
        }
        #pragma unroll
        for (int r = 0; r < 2; r++) {
            int idx = t + r * 256;
            int k   = idx >> 5;
            int j4  = idx & 31;
            *(float4*)&Bs[k][j4 * 4] =
                *(const float4*)(B + (size_t)(k0 + k) * 128 + j4 * 4);
        }
        __syncthreads();

        #pragma unroll
        for (int kk = 0; kk < 16; kk++) {
            float a[8];
            *(float4*)&a[0] = *(float4*)&As[kk][ty * 8];
            *(float4*)&a[4] = *(float4*)&As[kk][ty * 8 + 4];
            ulonglong2 blo = *(ulonglong2*)&Bs[kk][tx * 8];
            ulonglong2 bhi = *(ulonglong2*)&Bs[kk][tx * 8 + 4];
            unsigned long long b2[4] = {blo.x, blo.y, bhi.x, bhi.y};

            #pragma unroll
            for (int i = 0; i < 8; i++) {
                unsigned long long a2;
                asm("mov.b64 %0, {%1, %1};" : "=l"(a2) : "f"(a[i]));
                #pragma unroll
                for (int j = 0; j < 4; j++)
                    asm("fma.rn.f32x2 %0, %1, %2, %0;"
                        : "+l"(acc2[i][j]) : "l"(a2), "l"(b2[j]));
            }
        }
        __syncthreads();
    }

    #pragma unroll
    for (int i = 0; i < 8; i++) {
        int grow = m0 + ty * 8 + i;
        if (grow < NN) {
            float out[8];
            #pragma unroll
            for (int j = 0; j < 4; j++)
                asm("mov.b64 {%0, %1}, %2;"
                    : "=f"(out[2 * j]), "=f"(out[2 * j + 1]) : "l"(acc2[i][j]));
            float* dst = g_uv + (size_t)grow * 256 + q * 128 + tx * 8;
            *(float4*)dst       = *(float4*)&out[0];
            *(float4*)(dst + 4) = *(float4*)&out[4];
        }
    }
}

// ---------------------------------------------------------------------------
// K2: fused per-edge pass. EPW=4 edges per warp, gathers front-batched for MLP.
//   hidden = relu(u[src] + v[tgt] + w*W1c + b1); score = hidden.W2 + b2
//   es = exp(score); g_sum[tgt] += es; g_num[tgt] += es * x[src]
// ---------------------------------------------------------------------------
__global__ __launch_bounds__(256) void k_edge(
    const int* __restrict__ ei, const float* __restrict__ ew,
    const float* __restrict__ x,
    const float* __restrict__ W1, const float* __restrict__ b1,
    const float* __restrict__ W2, const float* __restrict__ b2)
{
    __shared__ float sW1c[HID], sb1[HID], sW2[HID];
    __shared__ float sb2;
    const int t = threadIdx.x;
    if (t < HID) {
        sW1c[t] = W1[256 * HID + t];
        sb1[t]  = b1[t];
        sW2[t]  = W2[t];
    }
    if (t == 0) sb2 = b2[0];
    __syncthreads();

    const int warp = t >> 5, lane = t & 31;
    const long e0 = ((long)blockIdx.x * 8 + warp) * EPW;
    if (e0 >= NE) return;   // grid sized exactly; defensive

    // ---- front-batched index / weight / gather loads (MLP ~14) ----
    int src[EPW], tgt[EPW];
    float w[EPW];
    #pragma unroll
    for (int j = 0; j < EPW; j++) {
        src[j] = ei[e0 + j];
        tgt[j] = ei[NE + e0 + j];
        w[j]   = ew[e0 + j];
    }

    float4 u[EPW], v[EPW], hx[EPW];
    #pragma unroll
    for (int j = 0; j < EPW; j++)
        u[j] = ((const float4*)(g_uv + (size_t)src[j] * 256))[lane];
    #pragma unroll
    for (int j = 0; j < EPW; j++)
        v[j] = ((const float4*)(g_uv + (size_t)tgt[j] * 256 + 128))[lane];
    #pragma unroll
    for (int j = 0; j < EPW; j++)
        hx[j] = ((const float4*)(x + (size_t)src[j] * HID))[lane];

    const float4 wc = *(const float4*)&sW1c[lane * 4];
    const float4 bb = *(const float4*)&sb1[lane * 4];
    const float4 w2 = *(const float4*)&sW2[lane * 4];

    // ---- 4 independent score computations (reduction chains interleave) ----
    float p[EPW];
    #pragma unroll
    for (int j = 0; j < EPW; j++) {
        float h0 = fmaxf(fmaf(w[j], wc.x, u[j].x + v[j].x) + bb.x, 0.0f);
        float h1 = fmaxf(fmaf(w[j], wc.y, u[j].y + v[j].y) + bb.y, 0.0f);
        float h2 = fmaxf(fmaf(w[j], wc.z, u[j].z + v[j].z) + bb.z, 0.0f);
        float h3 = fmaxf(fmaf(w[j], wc.w, u[j].w + v[j].w) + bb.w, 0.0f);
        p[j] = h0 * w2.x + h1 * w2.y + h2 * w2.z + h3 * w2.w;
    }
    #pragma unroll
    for (int o = 16; o; o >>= 1) {
        #pragma unroll
        for (int j = 0; j < EPW; j++)
            p[j] += __shfl_xor_sync(0xffffffffu, p[j], o);
    }

    float es[EPW];
    #pragma unroll
    for (int j = 0; j < EPW; j++) es[j] = expf(p[j] + sb2);

    // exp-sum atomics spread over lanes 0..EPW-1 (es[] is uniform across lanes)
    {
        float esx = es[0];
        int   tg  = tgt[0];
        #pragma unroll
        for (int j = 1; j < EPW; j++) {
            if (lane == j) { esx = es[j]; tg = tgt[j]; }
        }
        if (lane < EPW) atomicAdd(&g_sum[tg], esx);
    }

    // numerator scatter: vector reductions, 4 per lane
    #pragma unroll
    for (int j = 0; j < EPW; j++) {
        float* dst = g_num + (size_t)tgt[j] * HID + lane * 4;
        asm volatile("red.global.add.v4.f32 [%0], {%1, %2, %3, %4};"
                     :: "l"(dst), "f"(es[j] * hx[j].x), "f"(es[j] * hx[j].y),
                        "f"(es[j] * hx[j].z), "f"(es[j] * hx[j].w)
                     : "memory");
    }
}

// ---------------------------------------------------------------------------
// K3: normalize. out = x + g_num / max(g_sum, 1e-12)
// ---------------------------------------------------------------------------
__global__ void k_norm(const float* __restrict__ x, float* __restrict__ out) {
    long i = (long)blockIdx.x * blockDim.x + threadIdx.x;
    long stride = (long)gridDim.x * blockDim.x;
    const long n4 = (long)NN * HID / 4;
    const float4* x4 = (const float4*)x;
    const float4* num4 = (const float4*)g_num;
    float4* o4 = (float4*)out;
    for (long j = i; j < n4; j += stride) {
        int node = (int)(j >> 5);           // 32 float4 per node row
        float inv = 1.0f / fmaxf(g_sum[node], 1e-12f);
        float4 xv = x4[j];
        float4 nv = num4[j];
        o4[j] = make_float4(fmaf(nv.x, inv, xv.x), fmaf(nv.y, inv, xv.y),
                            fmaf(nv.z, inv, xv.z), fmaf(nv.w, inv, xv.w));
    }
}

// ---------------------------------------------------------------------------
extern "C" void kernel_launch(void* const* d_in, const int* in_sizes, int n_in,
                              void* d_out, int out_size)
{
    const float* x  = (const float*)d_in[0];
    const int*   ei = (const int*)d_in[1];
    const float* ew = (const float*)d_in[2];
    const float* W1 = (const float*)d_in[3];
    const float* b1 = (const float*)d_in[4];
    const float* W2 = (const float*)d_in[5];
    const float* b2 = (const float*)d_in[6];
    float* out = (float*)d_out;

    k_zero<<<2048, 256>>>();

    dim3 gg((NN + 127) / 128, 2);
    k_gemm<<<gg, 256>>>(x, W1);

    // NE = 600000 = 18750 blocks * 8 warps * 4 edges
    k_edge<<<NE / (8 * EPW), 256>>>(ei, ew, x, W1, b1, W2, b2);
    k_norm<<<2048, 256>>>(x, out);
}

// round 6
// speedup vs baseline: 1.5055x; 1.2861x over previous
#include <cuda_runtime.h>
#include <cuda_bf16.h>
#include <cstdint>

#define NN      100000
#define NE      600000
#define HID     128
#define EPW     4

// ---------------- scratch (device globals; no allocation allowed) ----------
__device__ float g_uv[(size_t)NN * 256];            // u (0..127) | v (128..255)
__device__ float g_num[(size_t)NN * HID];
__device__ float g_sum[NN];
__device__ __nv_bfloat16 g_xhi[(size_t)NN * 128];
__device__ __nv_bfloat16 g_xlo[(size_t)NN * 128];
__device__ __nv_bfloat16 g_Bhi[256 * 128];          // B[n][k] = W1[q*128+k][n&127]
__device__ __nv_bfloat16 g_Blo[256 * 128];

// ---------------------------------------------------------------------------
// K0: fused zero + bf16 hi/lo conversion (x and W1->B transposed)
// ---------------------------------------------------------------------------
__global__ void k_cvt(const float* __restrict__ x, const float* __restrict__ W1) {
    long i = (long)blockIdx.x * blockDim.x + threadIdx.x;
    long stride = (long)gridDim.x * blockDim.x;

    const long n4 = (long)NN * 32;
    float4* num4 = (float4*)g_num;
    const float4* x4 = (const float4*)x;
    const float4 z = make_float4(0.f, 0.f, 0.f, 0.f);

    for (long j = i; j < n4; j += stride) {
        num4[j] = z;
        float4 v = x4[j];
        __nv_bfloat16 h0 = __float2bfloat16_rn(v.x);
        __nv_bfloat16 h1 = __float2bfloat16_rn(v.y);
        __nv_bfloat16 h2 = __float2bfloat16_rn(v.z);
        __nv_bfloat16 h3 = __float2bfloat16_rn(v.w);
        __nv_bfloat16 l0 = __float2bfloat16_rn(v.x - __bfloat162float(h0));
        __nv_bfloat16 l1 = __float2bfloat16_rn(v.y - __bfloat162float(h1));
        __nv_bfloat16 l2 = __float2bfloat16_rn(v.z - __bfloat162float(h2));
        __nv_bfloat16 l3 = __float2bfloat16_rn(v.w - __bfloat162float(h3));
        __nv_bfloat162 hp0 = {h0, h1}, hp1 = {h2, h3};
        __nv_bfloat162 lp0 = {l0, l1}, lp1 = {l2, l3};
        ((uint2*)g_xhi)[j] = make_uint2(*(uint32_t*)&hp0, *(uint32_t*)&hp1);
        ((uint2*)g_xlo)[j] = make_uint2(*(uint32_t*)&lp0, *(uint32_t*)&lp1);
    }
    for (long j = i; j < NN; j += stride) g_sum[j] = 0.0f;
    for (long j = i; j < 256 * 128; j += stride) {
        int n = (int)(j >> 7), k = (int)(j & 127);
        int q = n >> 7, col = n & 127;
        float wv = W1[(size_t)(q * 128 + k) * 128 + col];
        __nv_bfloat16 h = __float2bfloat16_rn(wv);
        g_Bhi[j] = h;
        g_Blo[j] = __float2bfloat16_rn(wv - __bfloat162float(h));
    }
}

// ---------------------------------------------------------------------------
// K1: tensor-core GEMM via mma.sync bf16 (family-portable HMMA), 3-term split.
//   D[m][n] = sum_k A[m][k]*B[n][k];  A = xhi,xlo  B = Whi,Wlo (q half).
//   CTA 256 thr, tile 128x128; warps 4(m) x 2(n) -> warp tile 32x64.
//   SMEM rows padded to 272 B so fragment LDS.32 are bank-conflict-free.
// ---------------------------------------------------------------------------
#define ROWB      272                    // 128 bf16 = 256 B + 16 B pad
#define AS_OFF    0
#define BH_OFF    (128 * ROWB)           // 34816
#define BL_OFF    (2 * 128 * ROWB)       // 69632
#define SMEM_MMA  (3 * 128 * ROWB)       // 104448

__device__ __forceinline__ void mma_bf16(float* d, const uint32_t* a, const uint32_t* b) {
    asm volatile(
        "mma.sync.aligned.m16n8k16.row.col.f32.bf16.bf16.f32 "
        "{%0,%1,%2,%3}, {%4,%5,%6,%7}, {%8,%9}, {%0,%1,%2,%3};"
        : "+f"(d[0]), "+f"(d[1]), "+f"(d[2]), "+f"(d[3])
        : "r"(a[0]), "r"(a[1]), "r"(a[2]), "r"(a[3]), "r"(b[0]), "r"(b[1]));
}

__global__ __launch_bounds__(256, 2) void k_mma() {
    extern __shared__ char smem[];
    const int t = threadIdx.x;
    const int q = blockIdx.y;
    const int m0 = blockIdx.x * 128;

    // Load both B panels for this q (rows q*128 .. q*128+127), padded rows.
    #pragma unroll
    for (int r = 0; r < 8; r++) {
        int idx = t + r * 256;           // 0..2047
        int row = idx >> 4, c = idx & 15;
        *(uint4*)(smem + BH_OFF + row * ROWB + c * 16) =
            *(const uint4*)(g_Bhi + (size_t)(q * 128 + row) * 128 + c * 8);
        *(uint4*)(smem + BL_OFF + row * ROWB + c * 16) =
            *(const uint4*)(g_Blo + (size_t)(q * 128 + row) * 128 + c * 8);
    }

    const int wid = t >> 5, lane = t & 31;
    const int wm = (wid >> 1) * 32;      // warp m offset 0/32/64/96
    const int wn = (wid & 1) * 64;       // warp n offset 0/64
    const int g  = lane >> 2, tt = lane & 3;

    float acc[2][8][4];
    #pragma unroll
    for (int mt = 0; mt < 2; mt++)
        #pragma unroll
        for (int nt = 0; nt < 8; nt++)
            #pragma unroll
            for (int e = 0; e < 4; e++) acc[mt][nt][e] = 0.0f;

    #pragma unroll 1
    for (int pass = 0; pass < 2; pass++) {
        const __nv_bfloat16* Asrc = pass ? g_xlo : g_xhi;
        __syncthreads();                 // A buffer free / B visible
        #pragma unroll
        for (int r = 0; r < 8; r++) {
            int idx = t + r * 256;
            int row = idx >> 4, c = idx & 15;
            uint4 v = make_uint4(0, 0, 0, 0);
            if (m0 + row < NN)
                v = *(const uint4*)(Asrc + (size_t)(m0 + row) * 128 + c * 8);
            *(uint4*)(smem + AS_OFF + row * ROWB + c * 16) = v;
        }
        __syncthreads();

        const int nterms = pass ? 1 : 2;
        #pragma unroll 1
        for (int term = 0; term < nterms; term++) {
            const char* Bp = smem + ((pass == 0 && term == 1) ? BL_OFF : BH_OFF);
            #pragma unroll 1
            for (int ks = 0; ks < 8; ks++) {
                const int k0 = ks * 16;
                uint32_t a[2][4];
                #pragma unroll
                for (int mt = 0; mt < 2; mt++) {
                    const char* base = smem + AS_OFF +
                        (wm + mt * 16 + g) * ROWB + k0 * 2 + tt * 4;
                    a[mt][0] = *(const uint32_t*)(base);
                    a[mt][1] = *(const uint32_t*)(base + 8 * ROWB);
                    a[mt][2] = *(const uint32_t*)(base + 16);
                    a[mt][3] = *(const uint32_t*)(base + 8 * ROWB + 16);
                }
                uint32_t b[8][2];
                #pragma unroll
                for (int nt = 0; nt < 8; nt++) {
                    const char* base = Bp + (wn + nt * 8 + g) * ROWB + k0 * 2 + tt * 4;
                    b[nt][0] = *(const uint32_t*)(base);
                    b[nt][1] = *(const uint32_t*)(base + 16);
                }
                #pragma unroll
                for (int mt = 0; mt < 2; mt++)
                    #pragma unroll
                    for (int nt = 0; nt < 8; nt++)
                        mma_bf16(acc[mt][nt], a[mt], b[nt]);
            }
        }
    }

    // Epilogue: d0,d1 -> (row g, cols 2t,2t+1); d2,d3 -> row g+8.
    #pragma unroll
    for (int mt = 0; mt < 2; mt++) {
        const int r0 = m0 + wm + mt * 16 + g;
        #pragma unroll
        for (int nt = 0; nt < 8; nt++) {
            const int col = q * 128 + wn + nt * 8 + tt * 2;
            if (r0 < NN)
                *(float2*)(g_uv + (size_t)r0 * 256 + col) =
                    make_float2(acc[mt][nt][0], acc[mt][nt][1]);
            if (r0 + 8 < NN)
                *(float2*)(g_uv + (size_t)(r0 + 8) * 256 + col) =
                    make_float2(acc[mt][nt][2], acc[mt][nt][3]);
        }
    }
}

// ---------------------------------------------------------------------------
// K2: fused per-edge pass (EPW edges/warp, front-batched gathers)
// ---------------------------------------------------------------------------
__global__ __launch_bounds__(256) void k_edge(
    const int* __restrict__ ei, const float* __restrict__ ew,
    const float* __restrict__ x,
    const float* __restrict__ W1, const float* __restrict__ b1,
    const float* __restrict__ W2, const float* __restrict__ b2)
{
    __shared__ float sW1c[HID], sb1[HID], sW2[HID];
    __shared__ float sb2;
    const int t = threadIdx.x;
    if (t < HID) {
        sW1c[t] = W1[256 * HID + t];
        sb1[t]  = b1[t];
        sW2[t]  = W2[t];
    }
    if (t == 0) sb2 = b2[0];
    __syncthreads();

    const int warp = t >> 5, lane = t & 31;
    const long e0 = ((long)blockIdx.x * 8 + warp) * EPW;
    if (e0 >= NE) return;

    int src[EPW], tgt[EPW];
    float w[EPW];
    #pragma unroll
    for (int j = 0; j < EPW; j++) {
        src[j] = ei[e0 + j];
        tgt[j] = ei[NE + e0 + j];
        w[j]   = ew[e0 + j];
    }
    float4 u[EPW], v[EPW], hx[EPW];
    #pragma unroll
    for (int j = 0; j < EPW; j++)
        u[j] = ((const float4*)(g_uv + (size_t)src[j] * 256))[lane];
    #pragma unroll
    for (int j = 0; j < EPW; j++)
        v[j] = ((const float4*)(g_uv + (size_t)tgt[j] * 256 + 128))[lane];
    #pragma unroll
    for (int j = 0; j < EPW; j++)
        hx[j] = ((const float4*)(x + (size_t)src[j] * HID))[lane];

    const float4 wc = *(const float4*)&sW1c[lane * 4];
    const float4 bb = *(const float4*)&sb1[lane * 4];
    const float4 w2 = *(const float4*)&sW2[lane * 4];

    float p[EPW];
    #pragma unroll
    for (int j = 0; j < EPW; j++) {
        float h0 = fmaxf(fmaf(w[j], wc.x, u[j].x + v[j].x) + bb.x, 0.0f);
        float h1 = fmaxf(fmaf(w[j], wc.y, u[j].y + v[j].y) + bb.y, 0.0f);
        float h2 = fmaxf(fmaf(w[j], wc.z, u[j].z + v[j].z) + bb.z, 0.0f);
        float h3 = fmaxf(fmaf(w[j], wc.w, u[j].w + v[j].w) + bb.w, 0.0f);
        p[j] = h0 * w2.x + h1 * w2.y + h2 * w2.z + h3 * w2.w;
    }
    #pragma unroll
    for (int o = 16; o; o >>= 1) {
        #pragma unroll
        for (int j = 0; j < EPW; j++)
            p[j] += __shfl_xor_sync(0xffffffffu, p[j], o);
    }

    float es[EPW];
    #pragma unroll
    for (int j = 0; j < EPW; j++) es[j] = expf(p[j] + sb2);

    {
        float esx = es[0];
        int   tg  = tgt[0];
        #pragma unroll
        for (int j = 1; j < EPW; j++)
            if (lane == j) { esx = es[j]; tg = tgt[j]; }
        if (lane < EPW) atomicAdd(&g_sum[tg], esx);
    }
    #pragma unroll
    for (int j = 0; j < EPW; j++) {
        float* dst = g_num + (size_t)tgt[j] * HID + lane * 4;
        asm volatile("red.global.add.v4.f32 [%0], {%1, %2, %3, %4};"
                     :: "l"(dst), "f"(es[j] * hx[j].x), "f"(es[j] * hx[j].y),
                        "f"(es[j] * hx[j].z), "f"(es[j] * hx[j].w)
                     : "memory");
    }
}

// ---------------------------------------------------------------------------
// K3: normalize. out = x + g_num / max(g_sum, 1e-12)
// ---------------------------------------------------------------------------
__global__ void k_norm(const float* __restrict__ x, float* __restrict__ out) {
    long i = (long)blockIdx.x * blockDim.x + threadIdx.x;
    long stride = (long)gridDim.x * blockDim.x;
    const long n4 = (long)NN * HID / 4;
    const float4* x4 = (const float4*)x;
    const float4* num4 = (const float4*)g_num;
    float4* o4 = (float4*)out;
    for (long j = i; j < n4; j += stride) {
        int node = (int)(j >> 5);
        float inv = 1.0f / fmaxf(g_sum[node], 1e-12f);
        float4 xv = x4[j];
        float4 nv = num4[j];
        o4[j] = make_float4(fmaf(nv.x, inv, xv.x), fmaf(nv.y, inv, xv.y),
                            fmaf(nv.z, inv, xv.z), fmaf(nv.w, inv, xv.w));
    }
}

// ---------------------------------------------------------------------------
extern "C" void kernel_launch(void* const* d_in, const int* in_sizes, int n_in,
                              void* d_out, int out_size)
{
    const float* x  = (const float*)d_in[0];
    const int*   ei = (const int*)d_in[1];
    const float* ew = (const float*)d_in[2];
    const float* W1 = (const float*)d_in[3];
    const float* b1 = (const float*)d_in[4];
    const float* W2 = (const float*)d_in[5];
    const float* b2 = (const float*)d_in[6];
    float* out = (float*)d_out;

    cudaFuncSetAttribute(k_mma, cudaFuncAttributeMaxDynamicSharedMemorySize, SMEM_MMA);

    k_cvt<<<2048, 256>>>(x, W1);

    dim3 gg((NN + 127) / 128, 2);
    k_mma<<<gg, 256, SMEM_MMA>>>();

    k_edge<<<NE / (8 * EPW), 256>>>(ei, ew, x, W1, b1, W2, b2);
    k_norm<<<2048, 256>>>(x, out);
}

// round 7
// speedup vs baseline: 1.6851x; 1.1194x over previous
#include <cuda_runtime.h>
#include <cuda_bf16.h>
#include <cstdint>

#define NN      100000
#define NE      600000
#define HID     128
#define NSB     391              // scan blocks: ceil(NN/256)

// ---------------- scratch (device globals; no allocation allowed) ----------
__device__ float g_uv[(size_t)NN * 256];            // u (0..127) | v (128..255)
__device__ __nv_bfloat16 g_xhi[(size_t)NN * 128];
__device__ __nv_bfloat16 g_xlo[(size_t)NN * 128];
__device__ __nv_bfloat16 g_Bhi[256 * 128];          // B[n][k] = W1[q*128+k][n&127]
__device__ __nv_bfloat16 g_Blo[256 * 128];
__device__ int  g_cnt[NN];                          // per-tgt edge count
__device__ int  g_off[NN + 1];                      // CSR offsets (exclusive)
__device__ int  g_ptr[NN];                          // scatter cursors
__device__ int  g_bsum[NSB];                        // scan partials
__device__ int2 g_srcw[NE];                         // (src, bits(w)) grouped by tgt

// ---------------------------------------------------------------------------
// K0: bf16 hi/lo conversion (x, W1->B transposed) + zero histogram
// ---------------------------------------------------------------------------
__global__ void k_cvt(const float* __restrict__ x, const float* __restrict__ W1) {
    long i = (long)blockIdx.x * blockDim.x + threadIdx.x;
    long stride = (long)gridDim.x * blockDim.x;

    const long n4 = (long)NN * 32;
    const float4* x4 = (const float4*)x;
    for (long j = i; j < n4; j += stride) {
        float4 v = x4[j];
        __nv_bfloat16 h0 = __float2bfloat16_rn(v.x);
        __nv_bfloat16 h1 = __float2bfloat16_rn(v.y);
        __nv_bfloat16 h2 = __float2bfloat16_rn(v.z);
        __nv_bfloat16 h3 = __float2bfloat16_rn(v.w);
        __nv_bfloat16 l0 = __float2bfloat16_rn(v.x - __bfloat162float(h0));
        __nv_bfloat16 l1 = __float2bfloat16_rn(v.y - __bfloat162float(h1));
        __nv_bfloat16 l2 = __float2bfloat16_rn(v.z - __bfloat162float(h2));
        __nv_bfloat16 l3 = __float2bfloat16_rn(v.w - __bfloat162float(h3));
        __nv_bfloat162 hp0 = {h0, h1}, hp1 = {h2, h3};
        __nv_bfloat162 lp0 = {l0, l1}, lp1 = {l2, l3};
        ((uint2*)g_xhi)[j] = make_uint2(*(uint32_t*)&hp0, *(uint32_t*)&hp1);
        ((uint2*)g_xlo)[j] = make_uint2(*(uint32_t*)&lp0, *(uint32_t*)&lp1);
    }
    for (long j = i; j < NN; j += stride) g_cnt[j] = 0;
    for (long j = i; j < 256 * 128; j += stride) {
        int n = (int)(j >> 7), k = (int)(j & 127);
        int q = n >> 7, col = n & 127;
        float wv = W1[(size_t)(q * 128 + k) * 128 + col];
        __nv_bfloat16 h = __float2bfloat16_rn(wv);
        g_Bhi[j] = h;
        g_Blo[j] = __float2bfloat16_rn(wv - __bfloat162float(h));
    }
}

// ---------------------------------------------------------------------------
// CSR build: histogram -> scan (3 kernels) -> scatter
// ---------------------------------------------------------------------------
__global__ void k_hist(const int* __restrict__ ei) {
    long i = (long)blockIdx.x * blockDim.x + threadIdx.x;
    long stride = (long)gridDim.x * blockDim.x;
    for (long e = i; e < NE; e += stride)
        atomicAdd(&g_cnt[ei[NE + e]], 1);
}

__global__ void k_scan1() {
    const int b = blockIdx.x, t = threadIdx.x;
    const int i = b * 256 + t;
    int v = (i < NN) ? g_cnt[i] : 0;
    const int lane = t & 31, w = t >> 5;
    #pragma unroll
    for (int o = 1; o < 32; o <<= 1) {
        int n = __shfl_up_sync(0xffffffffu, v, o);
        if (lane >= o) v += n;
    }
    __shared__ int ws[8];
    if (lane == 31) ws[w] = v;
    __syncthreads();
    if (w == 0 && lane < 8) {
        int s = ws[lane];
        #pragma unroll
        for (int o = 1; o < 8; o <<= 1) {
            int n = __shfl_up_sync(0xffu, s, o);
            if (lane >= o) s += n;
        }
        ws[lane] = s;
    }
    __syncthreads();
    if (w > 0) v += ws[w - 1];
    if (i < NN) g_off[i + 1] = v;     // block-local inclusive
    if (t == 255) g_bsum[b] = v;      // block total
}

__global__ void k_scan2() {
    __shared__ int s[512];
    const int t = threadIdx.x;
    s[t] = (t < NSB) ? g_bsum[t] : 0;
    __syncthreads();
    #pragma unroll
    for (int o = 1; o < 512; o <<= 1) {
        int a = (t >= o) ? s[t - o] : 0;
        __syncthreads();
        s[t] += a;
        __syncthreads();
    }
    if (t < NSB) g_bsum[t] = s[t];
}

__global__ void k_scan3() {
    long i = (long)blockIdx.x * blockDim.x + threadIdx.x;
    long stride = (long)gridDim.x * blockDim.x;
    if (i == 0) g_off[0] = 0;
    for (long j = i; j < NN; j += stride) {
        int b = (int)(j >> 8);
        int incl = g_off[j + 1] + (b > 0 ? g_bsum[b - 1] : 0);
        g_off[j + 1] = incl;
        g_ptr[j] = incl - g_cnt[j];   // exclusive start = scatter cursor
    }
}

__global__ void k_scat(const int* __restrict__ ei, const float* __restrict__ ew) {
    long i = (long)blockIdx.x * blockDim.x + threadIdx.x;
    long stride = (long)gridDim.x * blockDim.x;
    for (long e = i; e < NE; e += stride) {
        int tg = ei[NE + e];
        int pos = atomicAdd(&g_ptr[tg], 1);
        g_srcw[pos] = make_int2(ei[e], __float_as_int(ew[e]));
    }
}

// ---------------------------------------------------------------------------
// K1: tensor-core GEMM via mma.sync bf16, 3-term split (unchanged from R6).
// ---------------------------------------------------------------------------
#define ROWB      272
#define AS_OFF    0
#define BH_OFF    (128 * ROWB)
#define BL_OFF    (2 * 128 * ROWB)
#define SMEM_MMA  (3 * 128 * ROWB)

__device__ __forceinline__ void mma_bf16(float* d, const uint32_t* a, const uint32_t* b) {
    asm volatile(
        "mma.sync.aligned.m16n8k16.row.col.f32.bf16.bf16.f32 "
        "{%0,%1,%2,%3}, {%4,%5,%6,%7}, {%8,%9}, {%0,%1,%2,%3};"
        : "+f"(d[0]), "+f"(d[1]), "+f"(d[2]), "+f"(d[3])
        : "r"(a[0]), "r"(a[1]), "r"(a[2]), "r"(a[3]), "r"(b[0]), "r"(b[1]));
}

__global__ __launch_bounds__(256, 2) void k_mma() {
    extern __shared__ char smem[];
    const int t = threadIdx.x;
    const int q = blockIdx.y;
    const int m0 = blockIdx.x * 128;

    #pragma unroll
    for (int r = 0; r < 8; r++) {
        int idx = t + r * 256;
        int row = idx >> 4, c = idx & 15;
        *(uint4*)(smem + BH_OFF + row * ROWB + c * 16) =
            *(const uint4*)(g_Bhi + (size_t)(q * 128 + row) * 128 + c * 8);
        *(uint4*)(smem + BL_OFF + row * ROWB + c * 16) =
            *(const uint4*)(g_Blo + (size_t)(q * 128 + row) * 128 + c * 8);
    }

    const int wid = t >> 5, lane = t & 31;
    const int wm = (wid >> 1) * 32;
    const int wn = (wid & 1) * 64;
    const int g  = lane >> 2, tt = lane & 3;

    float acc[2][8][4];
    #pragma unroll
    for (int mt = 0; mt < 2; mt++)
        #pragma unroll
        for (int nt = 0; nt < 8; nt++)
            #pragma unroll
            for (int e = 0; e < 4; e++) acc[mt][nt][e] = 0.0f;

    #pragma unroll 1
    for (int pass = 0; pass < 2; pass++) {
        const __nv_bfloat16* Asrc = pass ? g_xlo : g_xhi;
        __syncthreads();
        #pragma unroll
        for (int r = 0; r < 8; r++) {
            int idx = t + r * 256;
            int row = idx >> 4, c = idx & 15;
            uint4 v = make_uint4(0, 0, 0, 0);
            if (m0 + row < NN)
                v = *(const uint4*)(Asrc + (size_t)(m0 + row) * 128 + c * 8);
            *(uint4*)(smem + AS_OFF + row * ROWB + c * 16) = v;
        }
        __syncthreads();

        const int nterms = pass ? 1 : 2;
        #pragma unroll 1
        for (int term = 0; term < nterms; term++) {
            const char* Bp = smem + ((pass == 0 && term == 1) ? BL_OFF : BH_OFF);
            #pragma unroll 1
            for (int ks = 0; ks < 8; ks++) {
                const int k0 = ks * 16;
                uint32_t a[2][4];
                #pragma unroll
                for (int mt = 0; mt < 2; mt++) {
                    const char* base = smem + AS_OFF +
                        (wm + mt * 16 + g) * ROWB + k0 * 2 + tt * 4;
                    a[mt][0] = *(const uint32_t*)(base);
                    a[mt][1] = *(const uint32_t*)(base + 8 * ROWB);
                    a[mt][2] = *(const uint32_t*)(base + 16);
                    a[mt][3] = *(const uint32_t*)(base + 8 * ROWB + 16);
                }
                uint32_t b[8][2];
                #pragma unroll
                for (int nt = 0; nt < 8; nt++) {
                    const char* base = Bp + (wn + nt * 8 + g) * ROWB + k0 * 2 + tt * 4;
                    b[nt][0] = *(const uint32_t*)(base);
                    b[nt][1] = *(const uint32_t*)(base + 16);
                }
                #pragma unroll
                for (int mt = 0; mt < 2; mt++)
                    #pragma unroll
                    for (int nt = 0; nt < 8; nt++)
                        mma_bf16(acc[mt][nt], a[mt], b[nt]);
            }
        }
    }

    #pragma unroll
    for (int mt = 0; mt < 2; mt++) {
        const int r0 = m0 + wm + mt * 16 + g;
        #pragma unroll
        for (int nt = 0; nt < 8; nt++) {
            const int col = q * 128 + wn + nt * 8 + tt * 2;
            if (r0 < NN)
                *(float2*)(g_uv + (size_t)r0 * 256 + col) =
                    make_float2(acc[mt][nt][0], acc[mt][nt][1]);
            if (r0 + 8 < NN)
                *(float2*)(g_uv + (size_t)(r0 + 8) * 256 + col) =
                    make_float2(acc[mt][nt][2], acc[mt][nt][3]);
        }
    }
}

// ---------------------------------------------------------------------------
// K2: per-TARGET warp. v loaded once; sum & numerator in registers;
//     writes out = x[tgt] + num/sum directly (no atomics, no norm pass).
// ---------------------------------------------------------------------------
__global__ __launch_bounds__(256) void k_edge2(
    const float* __restrict__ x,
    const float* __restrict__ W1, const float* __restrict__ b1,
    const float* __restrict__ W2, const float* __restrict__ b2,
    float* __restrict__ out)
{
    __shared__ float sW1c[HID], sb1[HID], sW2[HID];
    __shared__ float sb2;
    const int t = threadIdx.x;
    if (t < HID) {
        sW1c[t] = W1[256 * HID + t];
        sb1[t]  = b1[t];
        sW2[t]  = W2[t];
    }
    if (t == 0) sb2 = b2[0];
    __syncthreads();

    const int warp = t >> 5, lane = t & 31;
    const int node = blockIdx.x * 8 + warp;      // grid sized so node < NN always

    const int beg = g_off[node], end = g_off[node + 1];

    const float4 v  = ((const float4*)(g_uv + (size_t)node * 256 + 128))[lane];
    const float4 xt = ((const float4*)(x + (size_t)node * HID))[lane];
    const float4 wc = *(const float4*)&sW1c[lane * 4];
    const float4 bb = *(const float4*)&sb1[lane * 4];
    const float4 w2 = *(const float4*)&sW2[lane * 4];
    const float  lb2 = sb2;

    float sum = 0.0f;
    float4 num = make_float4(0.f, 0.f, 0.f, 0.f);

    int i = beg;
    for (; i + 2 <= end; i += 2) {
        const int2 sw0 = g_srcw[i];
        const int2 sw1 = g_srcw[i + 1];
        const float w0 = __int_as_float(sw0.y);
        const float w1 = __int_as_float(sw1.y);
        const float4 u0 = ((const float4*)(g_uv + (size_t)sw0.x * 256))[lane];
        const float4 u1 = ((const float4*)(g_uv + (size_t)sw1.x * 256))[lane];
        const float4 h0 = ((const float4*)(x + (size_t)sw0.x * HID))[lane];
        const float4 h1 = ((const float4*)(x + (size_t)sw1.x * HID))[lane];

        float a0 = fmaxf(fmaf(w0, wc.x, u0.x + v.x) + bb.x, 0.f);
        float a1 = fmaxf(fmaf(w0, wc.y, u0.y + v.y) + bb.y, 0.f);
        float a2 = fmaxf(fmaf(w0, wc.z, u0.z + v.z) + bb.z, 0.f);
        float a3 = fmaxf(fmaf(w0, wc.w, u0.w + v.w) + bb.w, 0.f);
        float p0 = a0 * w2.x + a1 * w2.y + a2 * w2.z + a3 * w2.w;

        float c0 = fmaxf(fmaf(w1, wc.x, u1.x + v.x) + bb.x, 0.f);
        float c1 = fmaxf(fmaf(w1, wc.y, u1.y + v.y) + bb.y, 0.f);
        float c2 = fmaxf(fmaf(w1, wc.z, u1.z + v.z) + bb.z, 0.f);
        float c3 = fmaxf(fmaf(w1, wc.w, u1.w + v.w) + bb.w, 0.f);
        float p1 = c0 * w2.x + c1 * w2.y + c2 * w2.z + c3 * w2.w;

        #pragma unroll
        for (int o = 16; o; o >>= 1) {
            p0 += __shfl_xor_sync(0xffffffffu, p0, o);
            p1 += __shfl_xor_sync(0xffffffffu, p1, o);
        }
        const float e0 = expf(p0 + lb2);
        const float e1 = expf(p1 + lb2);
        sum += e0 + e1;
        num.x += e0 * h0.x + e1 * h1.x;
        num.y += e0 * h0.y + e1 * h1.y;
        num.z += e0 * h0.z + e1 * h1.z;
        num.w += e0 * h0.w + e1 * h1.w;
    }
    if (i < end) {
        const int2 sw0 = g_srcw[i];
        const float w0 = __int_as_float(sw0.y);
        const float4 u0 = ((const float4*)(g_uv + (size_t)sw0.x * 256))[lane];
        const float4 h0 = ((const float4*)(x + (size_t)sw0.x * HID))[lane];
        float a0 = fmaxf(fmaf(w0, wc.x, u0.x + v.x) + bb.x, 0.f);
        float a1 = fmaxf(fmaf(w0, wc.y, u0.y + v.y) + bb.y, 0.f);
        float a2 = fmaxf(fmaf(w0, wc.z, u0.z + v.z) + bb.z, 0.f);
        float a3 = fmaxf(fmaf(w0, wc.w, u0.w + v.w) + bb.w, 0.f);
        float p0 = a0 * w2.x + a1 * w2.y + a2 * w2.z + a3 * w2.w;
        #pragma unroll
        for (int o = 16; o; o >>= 1) p0 += __shfl_xor_sync(0xffffffffu, p0, o);
        const float e0 = expf(p0 + lb2);
        sum += e0;
        num.x += e0 * h0.x; num.y += e0 * h0.y;
        num.z += e0 * h0.z; num.w += e0 * h0.w;
    }

    const float inv = 1.0f / fmaxf(sum, 1e-12f);
    float4 o4 = make_float4(fmaf(num.x, inv, xt.x), fmaf(num.y, inv, xt.y),
                            fmaf(num.z, inv, xt.z), fmaf(num.w, inv, xt.w));
    ((float4*)(out + (size_t)node * HID))[lane] = o4;
}

// ---------------------------------------------------------------------------
extern "C" void kernel_launch(void* const* d_in, const int* in_sizes, int n_in,
                              void* d_out, int out_size)
{
    const float* x  = (const float*)d_in[0];
    const int*   ei = (const int*)d_in[1];
    const float* ew = (const float*)d_in[2];
    const float* W1 = (const float*)d_in[3];
    const float* b1 = (const float*)d_in[4];
    const float* W2 = (const float*)d_in[5];
    const float* b2 = (const float*)d_in[6];
    float* out = (float*)d_out;

    cudaFuncSetAttribute(k_mma, cudaFuncAttributeMaxDynamicSharedMemorySize, SMEM_MMA);

    k_cvt<<<2048, 256>>>(x, W1);
    k_hist<<<1024, 256>>>(ei);
    k_scan1<<<NSB, 256>>>();
    k_scan2<<<1, 512>>>();
    k_scan3<<<256, 256>>>();
    k_scat<<<1024, 256>>>(ei, ew);

    dim3 gg((NN + 127) / 128, 2);
    k_mma<<<gg, 256, SMEM_MMA>>>();

    k_edge2<<<NN / 8, 256>>>(x, W1, b1, W2, b2, out);
}

// round 8
// speedup vs baseline: 1.8510x; 1.0984x over previous
#include <cuda_runtime.h>
#include <cuda_bf16.h>
#include <cuda_fp16.h>
#include <cstdint>

#define NN      100000
#define NE      600000
#define HID     128
#define NSB     391              // scan blocks: ceil(NN/256)

// ---------------- scratch (device globals; no allocation allowed) ----------
// g_ux[node]: 32 chunks of 16B; chunk c = { u[4c..4c+3], x[4c..4c+3] } in fp16.
__device__ __half g_ux[(size_t)NN * 256];
__device__ float  g_v[(size_t)NN * 128];            // v = x @ W1b, fp32
__device__ __nv_bfloat16 g_xhi[(size_t)NN * 128];
__device__ __nv_bfloat16 g_xlo[(size_t)NN * 128];
__device__ __nv_bfloat16 g_Bhi[256 * 128];          // B[n][k] = W1[q*128+k][n&127]
__device__ __nv_bfloat16 g_Blo[256 * 128];
__device__ int  g_cnt[NN];
__device__ int  g_off[NN + 1];
__device__ int  g_ptr[NN];
__device__ int  g_bsum[NSB];
__device__ int2 g_srcw[NE];                         // (src, bits(w)) grouped by tgt

// ---------------------------------------------------------------------------
// K0: bf16 hi/lo conversion of x + fp16 x into g_ux + W1->B hi/lo + zero cnt
// ---------------------------------------------------------------------------
__global__ void k_cvt(const float* __restrict__ x, const float* __restrict__ W1) {
    long i = (long)blockIdx.x * blockDim.x + threadIdx.x;
    long stride = (long)gridDim.x * blockDim.x;

    const long n4 = (long)NN * 32;
    const float4* x4 = (const float4*)x;
    for (long j = i; j < n4; j += stride) {
        float4 v = x4[j];
        __nv_bfloat16 h0 = __float2bfloat16_rn(v.x);
        __nv_bfloat16 h1 = __float2bfloat16_rn(v.y);
        __nv_bfloat16 h2 = __float2bfloat16_rn(v.z);
        __nv_bfloat16 h3 = __float2bfloat16_rn(v.w);
        __nv_bfloat16 l0 = __float2bfloat16_rn(v.x - __bfloat162float(h0));
        __nv_bfloat16 l1 = __float2bfloat16_rn(v.y - __bfloat162float(h1));
        __nv_bfloat16 l2 = __float2bfloat16_rn(v.z - __bfloat162float(h2));
        __nv_bfloat16 l3 = __float2bfloat16_rn(v.w - __bfloat162float(h3));
        __nv_bfloat162 hp0 = {h0, h1}, hp1 = {h2, h3};
        __nv_bfloat162 lp0 = {l0, l1}, lp1 = {l2, l3};
        ((uint2*)g_xhi)[j] = make_uint2(*(uint32_t*)&hp0, *(uint32_t*)&hp1);
        ((uint2*)g_xlo)[j] = make_uint2(*(uint32_t*)&lp0, *(uint32_t*)&lp1);

        // fp16 x into g_ux chunk second half
        __half2 xh01 = __floats2half2_rn(v.x, v.y);
        __half2 xh23 = __floats2half2_rn(v.z, v.w);
        long node = j >> 5, c = j & 31;
        uint2 pk = make_uint2(*(uint32_t*)&xh01, *(uint32_t*)&xh23);
        *(uint2*)((char*)g_ux + (size_t)node * 512 + c * 16 + 8) = pk;
    }
    for (long j = i; j < NN; j += stride) g_cnt[j] = 0;
    for (long j = i; j < 256 * 128; j += stride) {
        int n = (int)(j >> 7), k = (int)(j & 127);
        int q = n >> 7, col = n & 127;
        float wv = W1[(size_t)(q * 128 + k) * 128 + col];
        __nv_bfloat16 h = __float2bfloat16_rn(wv);
        g_Bhi[j] = h;
        g_Blo[j] = __float2bfloat16_rn(wv - __bfloat162float(h));
    }
}

// ---------------------------------------------------------------------------
// CSR build: histogram -> scan (3 kernels) -> scatter
// ---------------------------------------------------------------------------
__global__ void k_hist(const int* __restrict__ ei) {
    long i = (long)blockIdx.x * blockDim.x + threadIdx.x;
    long stride = (long)gridDim.x * blockDim.x;
    for (long e = i; e < NE; e += stride)
        atomicAdd(&g_cnt[ei[NE + e]], 1);
}

__global__ void k_scan1() {
    const int b = blockIdx.x, t = threadIdx.x;
    const int i = b * 256 + t;
    int v = (i < NN) ? g_cnt[i] : 0;
    const int lane = t & 31, w = t >> 5;
    #pragma unroll
    for (int o = 1; o < 32; o <<= 1) {
        int n = __shfl_up_sync(0xffffffffu, v, o);
        if (lane >= o) v += n;
    }
    __shared__ int ws[8];
    if (lane == 31) ws[w] = v;
    __syncthreads();
    if (w == 0 && lane < 8) {
        int s = ws[lane];
        #pragma unroll
        for (int o = 1; o < 8; o <<= 1) {
            int n = __shfl_up_sync(0xffu, s, o);
            if (lane >= o) s += n;
        }
        ws[lane] = s;
    }
    __syncthreads();
    if (w > 0) v += ws[w - 1];
    if (i < NN) g_off[i + 1] = v;
    if (t == 255) g_bsum[b] = v;
}

__global__ void k_scan2() {
    __shared__ int s[512];
    const int t = threadIdx.x;
    s[t] = (t < NSB) ? g_bsum[t] : 0;
    __syncthreads();
    #pragma unroll
    for (int o = 1; o < 512; o <<= 1) {
        int a = (t >= o) ? s[t - o] : 0;
        __syncthreads();
        s[t] += a;
        __syncthreads();
    }
    if (t < NSB) g_bsum[t] = s[t];
}

__global__ void k_scan3() {
    long i = (long)blockIdx.x * blockDim.x + threadIdx.x;
    long stride = (long)gridDim.x * blockDim.x;
    if (i == 0) g_off[0] = 0;
    for (long j = i; j < NN; j += stride) {
        int b = (int)(j >> 8);
        int incl = g_off[j + 1] + (b > 0 ? g_bsum[b - 1] : 0);
        g_off[j + 1] = incl;
        g_ptr[j] = incl - g_cnt[j];
    }
}

__global__ void k_scat(const int* __restrict__ ei, const float* __restrict__ ew) {
    long i = (long)blockIdx.x * blockDim.x + threadIdx.x;
    long stride = (long)gridDim.x * blockDim.x;
    for (long e = i; e < NE; e += stride) {
        int tg = ei[NE + e];
        int pos = atomicAdd(&g_ptr[tg], 1);
        g_srcw[pos] = make_int2(ei[e], __float_as_int(ew[e]));
    }
}

// ---------------------------------------------------------------------------
// K1: tensor-core GEMM (mma.sync bf16, 3-term split).
//   q=0 -> u, stored fp16 into g_ux chunks; q=1 -> v, stored fp32 to g_v.
// ---------------------------------------------------------------------------
#define ROWB      272
#define AS_OFF    0
#define BH_OFF    (128 * ROWB)
#define BL_OFF    (2 * 128 * ROWB)
#define SMEM_MMA  (3 * 128 * ROWB)

__device__ __forceinline__ void mma_bf16(float* d, const uint32_t* a, const uint32_t* b) {
    asm volatile(
        "mma.sync.aligned.m16n8k16.row.col.f32.bf16.bf16.f32 "
        "{%0,%1,%2,%3}, {%4,%5,%6,%7}, {%8,%9}, {%0,%1,%2,%3};"
        : "+f"(d[0]), "+f"(d[1]), "+f"(d[2]), "+f"(d[3])
        : "r"(a[0]), "r"(a[1]), "r"(a[2]), "r"(a[3]), "r"(b[0]), "r"(b[1]));
}

__global__ __launch_bounds__(256, 2) void k_mma() {
    extern __shared__ char smem[];
    const int t = threadIdx.x;
    const int q = blockIdx.y;
    const int m0 = blockIdx.x * 128;

    #pragma unroll
    for (int r = 0; r < 8; r++) {
        int idx = t + r * 256;
        int row = idx >> 4, c = idx & 15;
        *(uint4*)(smem + BH_OFF + row * ROWB + c * 16) =
            *(const uint4*)(g_Bhi + (size_t)(q * 128 + row) * 128 + c * 8);
        *(uint4*)(smem + BL_OFF + row * ROWB + c * 16) =
            *(const uint4*)(g_Blo + (size_t)(q * 128 + row) * 128 + c * 8);
    }

    const int wid = t >> 5, lane = t & 31;
    const int wm = (wid >> 1) * 32;
    const int wn = (wid & 1) * 64;
    const int g  = lane >> 2, tt = lane & 3;

    float acc[2][8][4];
    #pragma unroll
    for (int mt = 0; mt < 2; mt++)
        #pragma unroll
        for (int nt = 0; nt < 8; nt++)
            #pragma unroll
            for (int e = 0; e < 4; e++) acc[mt][nt][e] = 0.0f;

    #pragma unroll 1
    for (int pass = 0; pass < 2; pass++) {
        const __nv_bfloat16* Asrc = pass ? g_xlo : g_xhi;
        __syncthreads();
        #pragma unroll
        for (int r = 0; r < 8; r++) {
            int idx = t + r * 256;
            int row = idx >> 4, c = idx & 15;
            uint4 v = make_uint4(0, 0, 0, 0);
            if (m0 + row < NN)
                v = *(const uint4*)(Asrc + (size_t)(m0 + row) * 128 + c * 8);
            *(uint4*)(smem + AS_OFF + row * ROWB + c * 16) = v;
        }
        __syncthreads();

        const int nterms = pass ? 1 : 2;
        #pragma unroll 1
        for (int term = 0; term < nterms; term++) {
            const char* Bp = smem + ((pass == 0 && term == 1) ? BL_OFF : BH_OFF);
            #pragma unroll 1
            for (int ks = 0; ks < 8; ks++) {
                const int k0 = ks * 16;
                uint32_t a[2][4];
                #pragma unroll
                for (int mt = 0; mt < 2; mt++) {
                    const char* base = smem + AS_OFF +
                        (wm + mt * 16 + g) * ROWB + k0 * 2 + tt * 4;
                    a[mt][0] = *(const uint32_t*)(base);
                    a[mt][1] = *(const uint32_t*)(base + 8 * ROWB);
                    a[mt][2] = *(const uint32_t*)(base + 16);
                    a[mt][3] = *(const uint32_t*)(base + 8 * ROWB + 16);
                }
                uint32_t b[8][2];
                #pragma unroll
                for (int nt = 0; nt < 8; nt++) {
                    const char* base = Bp + (wn + nt * 8 + g) * ROWB + k0 * 2 + tt * 4;
                    b[nt][0] = *(const uint32_t*)(base);
                    b[nt][1] = *(const uint32_t*)(base + 16);
                }
                #pragma unroll
                for (int mt = 0; mt < 2; mt++)
                    #pragma unroll
                    for (int nt = 0; nt < 8; nt++)
                        mma_bf16(acc[mt][nt], a[mt], b[nt]);
            }
        }
    }

    #pragma unroll
    for (int mt = 0; mt < 2; mt++) {
        const int r0 = m0 + wm + mt * 16 + g;
        #pragma unroll
        for (int nt = 0; nt < 8; nt++) {
            const int ncol = wn + nt * 8 + tt * 2;      // 0..127, even
            if (q == 0) {
                const size_t off = (size_t)(ncol >> 2) * 16 + (size_t)(ncol & 3) * 2;
                if (r0 < NN) {
                    __half2 h = __floats2half2_rn(acc[mt][nt][0], acc[mt][nt][1]);
                    *(__half2*)((char*)g_ux + (size_t)r0 * 512 + off) = h;
                }
                if (r0 + 8 < NN) {
                    __half2 h = __floats2half2_rn(acc[mt][nt][2], acc[mt][nt][3]);
                    *(__half2*)((char*)g_ux + (size_t)(r0 + 8) * 512 + off) = h;
                }
            } else {
                if (r0 < NN)
                    *(float2*)(g_v + (size_t)r0 * 128 + ncol) =
                        make_float2(acc[mt][nt][0], acc[mt][nt][1]);
                if (r0 + 8 < NN)
                    *(float2*)(g_v + (size_t)(r0 + 8) * 128 + ncol) =
                        make_float2(acc[mt][nt][2], acc[mt][nt][3]);
            }
        }
    }
}

// ---------------------------------------------------------------------------
// K2: per-TARGET warp; single 16B gather per edge per lane from L2-resident
//     packed fp16 [u|x]; fp32 accumulation; writes out directly.
// ---------------------------------------------------------------------------
__global__ __launch_bounds__(256) void k_edge2(
    const float* __restrict__ x,
    const float* __restrict__ W1, const float* __restrict__ b1,
    const float* __restrict__ W2, const float* __restrict__ b2,
    float* __restrict__ out)
{
    __shared__ float sW1c[HID], sb1[HID], sW2[HID];
    __shared__ float sb2;
    const int t = threadIdx.x;
    if (t < HID) {
        sW1c[t] = W1[256 * HID + t];
        sb1[t]  = b1[t];
        sW2[t]  = W2[t];
    }
    if (t == 0) sb2 = b2[0];
    __syncthreads();

    const int warp = t >> 5, lane = t & 31;
    const int node = blockIdx.x * 8 + warp;

    const int beg = g_off[node], end = g_off[node + 1];

    const float4 v  = ((const float4*)(g_v + (size_t)node * 128))[lane];
    const float4 xt = ((const float4*)(x + (size_t)node * HID))[lane];
    const float4 wc = *(const float4*)&sW1c[lane * 4];
    const float4 bb = *(const float4*)&sb1[lane * 4];
    const float4 w2 = *(const float4*)&sW2[lane * 4];
    const float  lb2 = sb2;

    float sum = 0.0f;
    float4 num = make_float4(0.f, 0.f, 0.f, 0.f);

    int i = beg;
    for (; i + 2 <= end; i += 2) {
        const int2 sw0 = g_srcw[i];
        const int2 sw1 = g_srcw[i + 1];
        const float w0 = __int_as_float(sw0.y);
        const float w1 = __int_as_float(sw1.y);
        const uint4 r0 = *(const uint4*)((const char*)g_ux + (size_t)sw0.x * 512 + lane * 16);
        const uint4 r1 = *(const uint4*)((const char*)g_ux + (size_t)sw1.x * 512 + lane * 16);

        float2 u0a = __half22float2(*(const __half2*)&r0.x);
        float2 u0b = __half22float2(*(const __half2*)&r0.y);
        float2 x0a = __half22float2(*(const __half2*)&r0.z);
        float2 x0b = __half22float2(*(const __half2*)&r0.w);
        float2 u1a = __half22float2(*(const __half2*)&r1.x);
        float2 u1b = __half22float2(*(const __half2*)&r1.y);
        float2 x1a = __half22float2(*(const __half2*)&r1.z);
        float2 x1b = __half22float2(*(const __half2*)&r1.w);

        float a0 = fmaxf(fmaf(w0, wc.x, u0a.x + v.x) + bb.x, 0.f);
        float a1 = fmaxf(fmaf(w0, wc.y, u0a.y + v.y) + bb.y, 0.f);
        float a2 = fmaxf(fmaf(w0, wc.z, u0b.x + v.z) + bb.z, 0.f);
        float a3 = fmaxf(fmaf(w0, wc.w, u0b.y + v.w) + bb.w, 0.f);
        float p0 = a0 * w2.x + a1 * w2.y + a2 * w2.z + a3 * w2.w;

        float c0 = fmaxf(fmaf(w1, wc.x, u1a.x + v.x) + bb.x, 0.f);
        float c1 = fmaxf(fmaf(w1, wc.y, u1a.y + v.y) + bb.y, 0.f);
        float c2 = fmaxf(fmaf(w1, wc.z, u1b.x + v.z) + bb.z, 0.f);
        float c3 = fmaxf(fmaf(w1, wc.w, u1b.y + v.w) + bb.w, 0.f);
        float p1 = c0 * w2.x + c1 * w2.y + c2 * w2.z + c3 * w2.w;

        #pragma unroll
        for (int o = 16; o; o >>= 1) {
            p0 += __shfl_xor_sync(0xffffffffu, p0, o);
            p1 += __shfl_xor_sync(0xffffffffu, p1, o);
        }
        const float e0 = expf(p0 + lb2);
        const float e1 = expf(p1 + lb2);
        sum += e0 + e1;
        num.x += e0 * x0a.x + e1 * x1a.x;
        num.y += e0 * x0a.y + e1 * x1a.y;
        num.z += e0 * x0b.x + e1 * x1b.x;
        num.w += e0 * x0b.y + e1 * x1b.y;
    }
    if (i < end) {
        const int2 sw0 = g_srcw[i];
        const float w0 = __int_as_float(sw0.y);
        const uint4 r0 = *(const uint4*)((const char*)g_ux + (size_t)sw0.x * 512 + lane * 16);
        float2 u0a = __half22float2(*(const __half2*)&r0.x);
        float2 u0b = __half22float2(*(const __half2*)&r0.y);
        float2 x0a = __half22float2(*(const __half2*)&r0.z);
        float2 x0b = __half22float2(*(const __half2*)&r0.w);
        float a0 = fmaxf(fmaf(w0, wc.x, u0a.x + v.x) + bb.x, 0.f);
        float a1 = fmaxf(fmaf(w0, wc.y, u0a.y + v.y) + bb.y, 0.f);
        float a2 = fmaxf(fmaf(w0, wc.z, u0b.x + v.z) + bb.z, 0.f);
        float a3 = fmaxf(fmaf(w0, wc.w, u0b.y + v.w) + bb.w, 0.f);
        float p0 = a0 * w2.x + a1 * w2.y + a2 * w2.z + a3 * w2.w;
        #pragma unroll
        for (int o = 16; o; o >>= 1) p0 += __shfl_xor_sync(0xffffffffu, p0, o);
        const float e0 = expf(p0 + lb2);
        sum += e0;
        num.x += e0 * x0a.x; num.y += e0 * x0a.y;
        num.z += e0 * x0b.x; num.w += e0 * x0b.y;
    }

    const float inv = 1.0f / fmaxf(sum, 1e-12f);
    float4 o4 = make_float4(fmaf(num.x, inv, xt.x), fmaf(num.y, inv, xt.y),
                            fmaf(num.z, inv, xt.z), fmaf(num.w, inv, xt.w));
    ((float4*)(out + (size_t)node * HID))[lane] = o4;
}

// ---------------------------------------------------------------------------
extern "C" void kernel_launch(void* const* d_in, const int* in_sizes, int n_in,
                              void* d_out, int out_size)
{
    const float* x  = (const float*)d_in[0];
    const int*   ei = (const int*)d_in[1];
    const float* ew = (const float*)d_in[2];
    const float* W1 = (const float*)d_in[3];
    const float* b1 = (const float*)d_in[4];
    const float* W2 = (const float*)d_in[5];
    const float* b2 = (const float*)d_in[6];
    float* out = (float*)d_out;

    cudaFuncSetAttribute(k_mma, cudaFuncAttributeMaxDynamicSharedMemorySize, SMEM_MMA);

    k_cvt<<<2048, 256>>>(x, W1);
    k_hist<<<1024, 256>>>(ei);
    k_scan1<<<NSB, 256>>>();
    k_scan2<<<1, 512>>>();
    k_scan3<<<256, 256>>>();
    k_scat<<<1024, 256>>>(ei, ew);

    dim3 gg((NN + 127) / 128, 2);
    k_mma<<<gg, 256, SMEM_MMA>>>();

    k_edge2<<<NN / 8, 256>>>(x, W1, b1, W2, b2, out);
}